// round 3
// baseline (speedup 1.0000x reference)
#include <cuda_runtime.h>

#define NQ      10
#define DIM     1024
#define NLAYERS 6
#define BATCH   16384

// 60 gate matrices: [layer][qubit][u00.re,u00.im,u01.re,u01.im,u10.re,u10.im,u11.re,u11.im]
__device__ __align__(16) float g_gates[NLAYERS][NQ][8];

// ---------------------------------------------------------------------------
// Packed f32x2 helpers (SASS FFMA2/FMUL2 — ptxas never emits these from C++)
// ---------------------------------------------------------------------------
__device__ __forceinline__ float2 ffma2_(float2 a, float2 b, float2 c) {
    float2 d;
    asm("{\n\t.reg .b64 A,B,C,D;\n\t"
        "mov.b64 A,{%2,%3};\n\t mov.b64 B,{%4,%5};\n\t mov.b64 C,{%6,%7};\n\t"
        "fma.rn.f32x2 D,A,B,C;\n\t"
        "mov.b64 {%0,%1},D;\n\t}"
        : "=f"(d.x), "=f"(d.y)
        : "f"(a.x), "f"(a.y), "f"(b.x), "f"(b.y), "f"(c.x), "f"(c.y));
    return d;
}
__device__ __forceinline__ float2 fmul2_(float2 a, float2 b) {
    float2 d;
    asm("{\n\t.reg .b64 A,B,D;\n\t"
        "mov.b64 A,{%2,%3};\n\t mov.b64 B,{%4,%5};\n\t"
        "mul.rn.f32x2 D,A,B;\n\t"
        "mov.b64 {%0,%1},D;\n\t}"
        : "=f"(d.x), "=f"(d.y)
        : "f"(a.x), "f"(a.y), "f"(b.x), "f"(b.y));
    return d;
}
__device__ __forceinline__ float2 fsub2_(float2 a, float2 b) {
    float2 d;
    asm("{\n\t.reg .b64 A,B,D;\n\t"
        "mov.b64 A,{%2,%3};\n\t mov.b64 B,{%4,%5};\n\t"
        "sub.rn.f32x2 D,A,B;\n\t"
        "mov.b64 {%0,%1},D;\n\t}"
        : "=f"(d.x), "=f"(d.y)
        : "f"(a.x), "f"(a.y), "f"(b.x), "f"(b.y));
    return d;
}
__device__ __forceinline__ float2 bc2(float v) { return make_float2(v, v); }

// ---------------------------------------------------------------------------
// Pre-kernel: build the 2x2 Rot matrices once.
// ---------------------------------------------------------------------------
__global__ void precompute_kernel(const float* __restrict__ qlayers) {
    int i = threadIdx.x;
    if (i >= NLAYERS * NQ) return;
    int l = i / NQ, w = i % NQ;
    float phi   = qlayers[(l * NQ + w) * 3 + 0];
    float theta = qlayers[(l * NQ + w) * 3 + 1];
    float omega = qlayers[(l * NQ + w) * 3 + 2];
    float s, c;  sincosf(0.5f * theta, &s, &c);
    float sp, cp; sincosf(0.5f * (phi + omega), &sp, &cp);
    float sm, cm; sincosf(0.5f * (phi - omega), &sm, &cm);
    float* g = g_gates[l][w];
    g[0] =  cp * c;  g[1] = -sp * c;   // u00
    g[2] = -cm * s;  g[3] = -sm * s;   // u01
    g[4] =  cm * s;  g[5] = -sm * s;   // u10
    g[6] =  cp * c;  g[7] =  sp * c;   // u11
}

// ---------------------------------------------------------------------------
// State layout: amplitude index n (10 bits).
//   bits 9..5 -> lane bits (lane bit B-5), bits 4..1 -> pack index k (bit B-1),
//   bit 0     -> f32x2 component.
// Qubit q acts on bit B = 9-q.
// ---------------------------------------------------------------------------

// lane-bit gate body for one pack (coeffs preselected per lane)
__device__ __forceinline__ void lane_gate_pack(
    float2& r, float2& i, unsigned msk,
    float2 mr2, float2 mi2, float2 pr2, float2 pi2)
{
    float2 qr, qi;
    qr.x = __shfl_xor_sync(0xffffffffu, r.x, msk);
    qr.y = __shfl_xor_sync(0xffffffffu, r.y, msk);
    qi.x = __shfl_xor_sync(0xffffffffu, i.x, msk);
    qi.y = __shfl_xor_sync(0xffffffffu, i.y, msk);
    float2 r0 = r, i0 = i;
    // re' = (mr*r0 + pr*qr) - (mi*i0 + pi*qi)
    r = fsub2_(ffma2_(pr2, qr, fmul2_(mr2, r0)),
               ffma2_(pi2, qi, fmul2_(mi2, i0)));
    // im' = mr*i0 + mi*r0 + pr*qi + pi*qr
    i = ffma2_(mr2, i0, ffma2_(mi2, r0, ffma2_(pr2, qi, fmul2_(pi2, qr))));
}

// local pair gate body on packs (k, k2), coeff packs broadcast
__device__ __forceinline__ void local_gate_pair(
    float2& ar, float2& ai, float2& br, float2& bi,
    float2 uax2, float2 uay2, float2 uaz2, float2 uaw2,
    float2 ubx2, float2 uby2, float2 ubz2, float2 ubw2)
{
    float2 Ar = ar, Ai = ai, Br = br, Bi = bi;
    ar = fsub2_(ffma2_(uaz2, Br, fmul2_(uax2, Ar)),
                ffma2_(uaw2, Bi, fmul2_(uay2, Ai)));
    ai = ffma2_(uax2, Ai, ffma2_(uay2, Ar,
                ffma2_(uaz2, Bi, fmul2_(uaw2, Br))));
    br = fsub2_(ffma2_(ubz2, Br, fmul2_(ubx2, Ar)),
                ffma2_(ubw2, Bi, fmul2_(uby2, Ai)));
    bi = ffma2_(ubx2, Ai, ffma2_(uby2, Ar,
                ffma2_(ubz2, Bi, fmul2_(ubw2, Br))));
}

// Fused pair P: lane gate (qubit P, bit 9-P, lane bit 4-P) interleaved with
// local gate (qubit 5+P). For P<4 the local gate is a pack-pair gate on pack
// bit 3-P; for P==4 it is the intra-pack (bit 0) gate. Gates on distinct
// qubits commute, so per-element order (lane gate first) is valid.
template<int P>
__device__ __forceinline__ void fused_pair(float2 sr[16], float2 si[16], int lane,
                                           const float4* __restrict__ gp) {
    const float4 ua = __ldg(gp + 2 * P);
    const float4 ub = __ldg(gp + 2 * P + 1);
    constexpr unsigned msk = 1u << (4 - P);
    const bool hi = (lane >> (4 - P)) & 1;
    const float2 mr2 = bc2(hi ? ub.z : ua.x);
    const float2 mi2 = bc2(hi ? ub.w : ua.y);
    const float2 pr2 = bc2(hi ? ub.x : ua.z);
    const float2 pi2 = bc2(hi ? ub.y : ua.w);

    constexpr int QP = 5 + P;
    const float4 va = __ldg(gp + 2 * QP);
    const float4 vb = __ldg(gp + 2 * QP + 1);

    if constexpr (P < 4) {
        constexpr int pb = 3 - P;
        const float2 vax2 = bc2(va.x), vay2 = bc2(va.y);
        const float2 vaz2 = bc2(va.z), vaw2 = bc2(va.w);
        const float2 vbx2 = bc2(vb.x), vby2 = bc2(vb.y);
        const float2 vbz2 = bc2(vb.z), vbw2 = bc2(vb.w);
        #pragma unroll
        for (int h = 0; h < 8; ++h) {
            const int k  = ((h >> pb) << (pb + 1)) | (h & ((1 << pb) - 1));
            const int k2 = k | (1 << pb);
            lane_gate_pack(sr[k],  si[k],  msk, mr2, mi2, pr2, pi2);
            lane_gate_pack(sr[k2], si[k2], msk, mr2, mi2, pr2, pi2);
            local_gate_pair(sr[k], si[k], sr[k2], si[k2],
                            vax2, vay2, vaz2, vaw2, vbx2, vby2, vbz2, vbw2);
        }
    } else {
        // intra-pack gate coefficients (component 0/1 mixed packs)
        const float2 C1r = make_float2(va.x, vb.z);
        const float2 C1i = make_float2(va.y, vb.w);
        const float2 C2r = make_float2(va.z, vb.x);
        const float2 C2i = make_float2(va.w, vb.y);
        #pragma unroll
        for (int k = 0; k < 16; ++k) {
            lane_gate_pack(sr[k], si[k], msk, mr2, mi2, pr2, pi2);
            float2 vr = sr[k], vi = si[k];
            float2 wr = make_float2(vr.y, vr.x);
            float2 wi = make_float2(vi.y, vi.x);
            sr[k] = fsub2_(ffma2_(C2r, wr, fmul2_(C1r, vr)),
                           ffma2_(C2i, wi, fmul2_(C1i, vi)));
            si[k] = ffma2_(C1r, vi, ffma2_(C1i, vr,
                           ffma2_(C2r, wi, fmul2_(C2i, wr))));
        }
    }
}

template<int P>
__device__ __forceinline__ void gate_layer(float2 sr[16], float2 si[16], int lane,
                                           const float4* __restrict__ gp) {
    if constexpr (P < 5) {
        fused_pair<P>(sr, si, lane, gp);
        gate_layer<P + 1>(sr, si, lane, gp);
    }
}

// ---------------------------------------------------------------------------
// CNOT: control bit BC, target bit BT (amplitude-bit indices).
// ---------------------------------------------------------------------------
template<int BC, int BT>
__device__ __forceinline__ void cnot_gate(float2 sr[16], float2 si[16], int lane) {
    if constexpr (BC >= 5 && BT >= 5) {
        constexpr unsigned msk = 1u << (BT - 5);
        const bool ctl = (lane >> (BC - 5)) & 1;
        #pragma unroll
        for (int k = 0; k < 16; ++k) {
            float2 qr, qi;
            qr.x = __shfl_xor_sync(0xffffffffu, sr[k].x, msk);
            qr.y = __shfl_xor_sync(0xffffffffu, sr[k].y, msk);
            qi.x = __shfl_xor_sync(0xffffffffu, si[k].x, msk);
            qi.y = __shfl_xor_sync(0xffffffffu, si[k].y, msk);
            sr[k].x = ctl ? qr.x : sr[k].x;  sr[k].y = ctl ? qr.y : sr[k].y;
            si[k].x = ctl ? qi.x : si[k].x;  si[k].y = ctl ? qi.y : si[k].y;
        }
    } else if constexpr (BC >= 5 && BT >= 1) {
        constexpr int pb = BT - 1;
        const bool ctl = (lane >> (BC - 5)) & 1;
        #pragma unroll
        for (int k = 0; k < 16; ++k) {
            if (!((k >> pb) & 1)) {
                const int k2 = k | (1 << pb);
                float2 r0 = sr[k], r1 = sr[k2];
                float2 i0 = si[k], i1 = si[k2];
                sr[k].x  = ctl ? r1.x : r0.x;  sr[k].y  = ctl ? r1.y : r0.y;
                sr[k2].x = ctl ? r0.x : r1.x;  sr[k2].y = ctl ? r0.y : r1.y;
                si[k].x  = ctl ? i1.x : i0.x;  si[k].y  = ctl ? i1.y : i0.y;
                si[k2].x = ctl ? i0.x : i1.x;  si[k2].y = ctl ? i0.y : i1.y;
            }
        }
    } else if constexpr (BC >= 5 && BT == 0) {
        const bool ctl = (lane >> (BC - 5)) & 1;
        #pragma unroll
        for (int k = 0; k < 16; ++k) {
            float2 vr = sr[k], vi = si[k];
            sr[k].x = ctl ? vr.y : vr.x;  sr[k].y = ctl ? vr.x : vr.y;
            si[k].x = ctl ? vi.y : vi.x;  si[k].y = ctl ? vi.x : vi.y;
        }
    } else if constexpr (BC >= 1 && BT >= 5) {
        constexpr unsigned msk = 1u << (BT - 5);
        constexpr int pb = BC - 1;
        #pragma unroll
        for (int k = 0; k < 16; ++k) {
            if ((k >> pb) & 1) {
                sr[k].x = __shfl_xor_sync(0xffffffffu, sr[k].x, msk);
                sr[k].y = __shfl_xor_sync(0xffffffffu, sr[k].y, msk);
                si[k].x = __shfl_xor_sync(0xffffffffu, si[k].x, msk);
                si[k].y = __shfl_xor_sync(0xffffffffu, si[k].y, msk);
            }
        }
    } else if constexpr (BC >= 1 && BT >= 1) {
        constexpr int pbc = BC - 1, pbt = BT - 1;
        #pragma unroll
        for (int k = 0; k < 16; ++k) {
            if (((k >> pbc) & 1) && !((k >> pbt) & 1)) {
                const int k2 = k | (1 << pbt);
                float2 t;
                t = sr[k]; sr[k] = sr[k2]; sr[k2] = t;
                t = si[k]; si[k] = si[k2]; si[k2] = t;
            }
        }
    } else if constexpr (BC >= 1 && BT == 0) {
        constexpr int pb = BC - 1;
        #pragma unroll
        for (int k = 0; k < 16; ++k) {
            if ((k >> pb) & 1) {
                float t;
                t = sr[k].x; sr[k].x = sr[k].y; sr[k].y = t;
                t = si[k].x; si[k].x = si[k].y; si[k].y = t;
            }
        }
    } else if constexpr (BC == 0 && BT >= 5) {
        constexpr unsigned msk = 1u << (BT - 5);
        #pragma unroll
        for (int k = 0; k < 16; ++k) {
            sr[k].y = __shfl_xor_sync(0xffffffffu, sr[k].y, msk);
            si[k].y = __shfl_xor_sync(0xffffffffu, si[k].y, msk);
        }
    } else {
        constexpr int pb = BT - 1;
        #pragma unroll
        for (int k = 0; k < 16; ++k) {
            if (!((k >> pb) & 1)) {
                const int k2 = k | (1 << pb);
                float t;
                t = sr[k].y; sr[k].y = sr[k2].y; sr[k2].y = t;
                t = si[k].y; si[k].y = si[k2].y; si[k2].y = t;
            }
        }
    }
}

template<int R, int W>
__device__ __forceinline__ void cnot_chain(float2 sr[16], float2 si[16], int lane) {
    if constexpr (W < NQ) {
        constexpr int T = (W + R) % NQ;
        cnot_gate<9 - W, 9 - T>(sr, si, lane);
        cnot_chain<R, W + 1>(sr, si, lane);
    }
}

// ---------------------------------------------------------------------------
// Main kernel: one warp per batch sample, state in registers (f32x2 packed).
// ---------------------------------------------------------------------------
__global__ void __launch_bounds__(256, 2) qcnn_kernel(
    const float* __restrict__ x,
    const float* __restrict__ fc_w,
    const float* __restrict__ fc_b,
    float* __restrict__ out)
{
    const int warp = (blockIdx.x * blockDim.x + threadIdx.x) >> 5;
    const int lane = threadIdx.x & 31;
    if (warp >= BATCH) return;

    // --- initial product state ---------------------------------------------
    const float* xb = x + warp * NQ;
    float cq[NQ], sq[NQ];
    #pragma unroll
    for (int q = 0; q < NQ; ++q) {
        float h = 0.5f * __ldg(xb + q);
        sincosf(h, &sq[q], &cq[q]);
    }
    float A = 1.f;
    #pragma unroll
    for (int q = 0; q < 5; ++q)
        A *= ((lane >> (4 - q)) & 1) ? sq[q] : cq[q];

    float m[16];
    m[0] = A;
    #pragma unroll
    for (int t = 0; t < 4; ++t) {
        const int q = 8 - t;
        const int sz = 1 << t;
        #pragma unroll
        for (int k = sz - 1; k >= 0; --k) {
            float v = m[k];
            m[k + sz] = v * sq[q];
            m[k]      = v * cq[q];
        }
    }
    const int pl = __popc(lane);
    float rmul[4], imul[4];
    #pragma unroll
    for (int c = 0; c < 4; ++c) {
        int kk = (pl + c) & 3;
        rmul[c] = (kk == 0) ? 1.f : ((kk == 2) ? -1.f : 0.f);
        imul[c] = (kk == 3) ? 1.f : ((kk == 1) ? -1.f : 0.f);
    }
    float2 sr[16], si[16];
    #pragma unroll
    for (int k = 0; k < 16; ++k) {
        const int c0 = __popc(k) & 3;
        const int c1 = (__popc(k) + 1) & 3;
        float mag0 = m[k] * cq[9];
        float mag1 = m[k] * sq[9];
        sr[k] = make_float2(mag0 * rmul[c0], mag1 * rmul[c1]);
        si[k] = make_float2(mag0 * imul[c0], mag1 * imul[c1]);
    }

    // --- circuit ------------------------------------------------------------
    #pragma unroll 1
    for (int l = 0; l < NLAYERS; ++l) {
        const float4* gp = reinterpret_cast<const float4*>(g_gates[l]);
        gate_layer<0>(sr, si, lane, gp);
        switch (l) {   // r = l+1 for l in 0..5
            case 0: cnot_chain<1, 0>(sr, si, lane); break;
            case 1: cnot_chain<2, 0>(sr, si, lane); break;
            case 2: cnot_chain<3, 0>(sr, si, lane); break;
            case 3: cnot_chain<4, 0>(sr, si, lane); break;
            case 4: cnot_chain<5, 0>(sr, si, lane); break;
            default: cnot_chain<6, 0>(sr, si, lane); break;
        }
    }

    // --- epilogue: sum_i w_i * |psi_i|^2 ------------------------------------
    float f[NQ];
    #pragma unroll
    for (int q = 0; q < NQ; ++q) f[q] = __ldg(fc_w + q);

    float wl = 0.f;
    #pragma unroll
    for (int q = 0; q < 5; ++q)
        wl += ((lane >> (4 - q)) & 1) ? -f[q] : f[q];

    float2 acc2 = make_float2(0.f, 0.f);
    #pragma unroll
    for (int k = 0; k < 16; ++k) {
        float base = wl;
        base += (k & 1) ? -f[8] : f[8];
        base += (k & 2) ? -f[7] : f[7];
        base += (k & 4) ? -f[6] : f[6];
        base += (k & 8) ? -f[5] : f[5];
        float2 w2 = make_float2(base + f[9], base - f[9]);
        float2 p2 = ffma2_(si[k], si[k], fmul2_(sr[k], sr[k]));
        acc2 = ffma2_(w2, p2, acc2);
    }
    float acc = acc2.x + acc2.y;
    #pragma unroll
    for (int off = 16; off; off >>= 1)
        acc += __shfl_xor_sync(0xffffffffu, acc, off);

    if (lane == 0) out[warp] = acc + __ldg(fc_b);
}

// ---------------------------------------------------------------------------
extern "C" void kernel_launch(void* const* d_in, const int* in_sizes, int n_in,
                              void* d_out, int out_size) {
    const float* x    = (const float*)d_in[0];   // (16384, 10)
    const float* ql   = (const float*)d_in[1];   // (6, 10, 3)
    const float* fcw  = (const float*)d_in[2];   // (1, 10)
    const float* fcb  = (const float*)d_in[3];   // (1,)
    float* out = (float*)d_out;                  // (16384, 1)

    precompute_kernel<<<1, 64>>>(ql);
    qcnn_kernel<<<BATCH / 8, 256>>>(x, fcw, fcb, out);
}

// round 4
// speedup vs baseline: 1.5477x; 1.5477x over previous
#include <cuda_runtime.h>

#define NQ      10
#define DIM     1024
#define NLAYERS 6
#define BATCH   16384

// Precomputed tables (sample-independent):
//  g_ry[l][q] = (cos θ/2, sin θ/2)
//  g_T0[idx]  = init phase pairs: (-i)^popc(n) * Dphi_0[n], packed per f32x2 pair
//  g_E[l-1][idx] = fused diagonal between RY layer l-1 and l (phase pairs)
// idx layout: idx = k*32 + lane;  pair covers amplitudes n0 = lane*32+k*2, n1 = n0+1
__device__ float2 g_ry[NLAYERS][NQ];
__device__ __align__(16) float4 g_T0[512];
__device__ __align__(16) float4 g_E[5][512];

// ---------------------------------------------------------------------------
// Packed f32x2 helpers (SASS FFMA2/FMUL2 — ptxas never emits these from C++)
// ---------------------------------------------------------------------------
__device__ __forceinline__ float2 ffma2_(float2 a, float2 b, float2 c) {
    float2 d;
    asm("{\n\t.reg .b64 A,B,C,D;\n\t"
        "mov.b64 A,{%2,%3};\n\t mov.b64 B,{%4,%5};\n\t mov.b64 C,{%6,%7};\n\t"
        "fma.rn.f32x2 D,A,B,C;\n\t"
        "mov.b64 {%0,%1},D;\n\t}"
        : "=f"(d.x), "=f"(d.y)
        : "f"(a.x), "f"(a.y), "f"(b.x), "f"(b.y), "f"(c.x), "f"(c.y));
    return d;
}
__device__ __forceinline__ float2 fmul2_(float2 a, float2 b) {
    float2 d;
    asm("{\n\t.reg .b64 A,B,D;\n\t"
        "mov.b64 A,{%2,%3};\n\t mov.b64 B,{%4,%5};\n\t"
        "mul.rn.f32x2 D,A,B;\n\t"
        "mov.b64 {%0,%1},D;\n\t}"
        : "=f"(d.x), "=f"(d.y)
        : "f"(a.x), "f"(a.y), "f"(b.x), "f"(b.y));
    return d;
}
__device__ __forceinline__ float2 fsub2_(float2 a, float2 b) {
    float2 d;
    asm("{\n\t.reg .b64 A,B,D;\n\t"
        "mov.b64 A,{%2,%3};\n\t mov.b64 B,{%4,%5};\n\t"
        "sub.rn.f32x2 D,A,B;\n\t"
        "mov.b64 {%0,%1},D;\n\t}"
        : "=f"(d.x), "=f"(d.y)
        : "f"(a.x), "f"(a.y), "f"(b.x), "f"(b.y));
    return d;
}
__device__ __forceinline__ float2 bc2(float v) { return make_float2(v, v); }

// ---------------------------------------------------------------------------
// Pre-kernel: RY coefficients + diagonal phase tables.
// ---------------------------------------------------------------------------
__device__ __forceinline__ float sum_signed(int n, const float* ql, int l, int off) {
    float a = 0.f;
    #pragma unroll
    for (int q = 0; q < NQ; ++q) {
        float v = ql[(l * NQ + q) * 3 + off];
        a += ((n >> (9 - q)) & 1) ? v : -v;
    }
    return 0.5f * a;
}

__global__ void table_kernel(const float* __restrict__ ql) {
    int idx = blockIdx.x * blockDim.x + threadIdx.x;
    if (idx < NLAYERS * NQ) {
        int l = idx / NQ, q = idx % NQ;
        float s, c; sincosf(0.5f * ql[(l * NQ + q) * 3 + 1], &s, &c);
        g_ry[l][q] = make_float2(c, s);
    }
    if (idx >= 512) return;
    int k = idx >> 5, lane = idx & 31;
    int n0 = lane * 32 + k * 2;

    // T0: (-i)^popc(n) * Dphi_0[n]
    {
        float cs[2], sn[2];
        #pragma unroll
        for (int comp = 0; comp < 2; ++comp) {
            int n = n0 + comp;
            float ang = -1.57079632679f * __popc(n) + sum_signed(n, ql, 0, 0);
            sincosf(ang, &sn[comp], &cs[comp]);
        }
        g_T0[idx] = make_float4(cs[0], sn[0], cs[1], sn[1]);
    }
    // E_l for l = 1..5: E[m] = Domega_{l-1}[m] * Dphi_l[sigma_{l-1}^{-1}(m)]
    #pragma unroll 1
    for (int l = 1; l <= 5; ++l) {
        float cs[2], sn[2];
        #pragma unroll
        for (int comp = 0; comp < 2; ++comp) {
            int n = n0 + comp;
            float angw = sum_signed(n, ql, l - 1, 2);
            int p = n;             // sigma^{-1}: apply tau_0 .. tau_9 in order
            #pragma unroll
            for (int w = 0; w < NQ; ++w) {
                int cbit = 9 - w;
                int tbit = 9 - ((w + l) % NQ);
                p ^= ((p >> cbit) & 1) << tbit;
            }
            float angp = sum_signed(p, ql, l, 0);
            sincosf(angw + angp, &sn[comp], &cs[comp]);
        }
        g_E[l - 1][idx] = make_float4(cs[0], sn[0], cs[1], sn[1]);
    }
}

// ---------------------------------------------------------------------------
// State layout: amplitude n: bits 9..5 lane, 4..1 pack k, 0 comp.
// Qubit q acts on bit 9-q.
// ---------------------------------------------------------------------------

// RY layer: qubits 0..4 on lane bits, 5..9 local.
template<int P>
__device__ __forceinline__ void ry_layer(float2 sr[16], float2 si[16], int lane,
                                         const float2* __restrict__ ry) {
    if constexpr (P < 5) {
        // lane gate: qubit P, lane bit 4-P
        const float2 g = __ldg(ry + P);
        constexpr unsigned msk = 1u << (4 - P);
        const bool hi = (lane >> (4 - P)) & 1;
        const float2 c2 = bc2(g.x);
        const float2 ss2 = bc2(hi ? g.y : -g.y);
        #pragma unroll
        for (int k = 0; k < 16; ++k) {
            float2 qr, qi;
            qr.x = __shfl_xor_sync(0xffffffffu, sr[k].x, msk);
            qr.y = __shfl_xor_sync(0xffffffffu, sr[k].y, msk);
            qi.x = __shfl_xor_sync(0xffffffffu, si[k].x, msk);
            qi.y = __shfl_xor_sync(0xffffffffu, si[k].y, msk);
            sr[k] = ffma2_(ss2, qr, fmul2_(c2, sr[k]));
            si[k] = ffma2_(ss2, qi, fmul2_(c2, si[k]));
        }
        // local gate: qubit 5+P
        const float2 h = __ldg(ry + 5 + P);
        if constexpr (P < 4) {
            constexpr int pb = 3 - P;
            const float2 cl2 = bc2(h.x);
            const float2 sl2 = bc2(h.y);
            const float2 nsl2 = bc2(-h.y);
            #pragma unroll
            for (int t = 0; t < 8; ++t) {
                const int k  = ((t >> pb) << (pb + 1)) | (t & ((1 << pb) - 1));
                const int k2 = k | (1 << pb);
                float2 Ar = sr[k], Ai = si[k], Br = sr[k2], Bi = si[k2];
                sr[k]  = ffma2_(nsl2, Br, fmul2_(cl2, Ar));   // A' = cA - sB
                si[k]  = ffma2_(nsl2, Bi, fmul2_(cl2, Ai));
                sr[k2] = ffma2_(cl2, Br, fmul2_(sl2, Ar));    // B' = sA + cB
                si[k2] = ffma2_(cl2, Bi, fmul2_(sl2, Ai));
            }
        } else {
            // qubit 9: comp bit. out = c*v + (-s,+s) .* swap(v)
            const float2 c2l = bc2(h.x);
            const float2 sp2 = make_float2(-h.y, h.y);
            #pragma unroll
            for (int k = 0; k < 16; ++k) {
                float2 vr = sr[k], vi = si[k];
                float2 wr = make_float2(vr.y, vr.x);
                float2 wi = make_float2(vi.y, vi.x);
                sr[k] = ffma2_(sp2, wr, fmul2_(c2l, vr));
                si[k] = ffma2_(sp2, wi, fmul2_(c2l, vi));
            }
        }
        ry_layer<P + 1>(sr, si, lane, ry);
    }
}

// fused diagonal: per pack complex multiply by table phase
__device__ __forceinline__ void apply_diag(float2 sr[16], float2 si[16], int lane,
                                           const float4* __restrict__ tbl) {
    #pragma unroll
    for (int k = 0; k < 16; ++k) {
        float4 t = __ldg(tbl + k * 32 + lane);
        float2 c = make_float2(t.x, t.z);
        float2 s = make_float2(t.y, t.w);
        float2 r = sr[k], i = si[k];
        sr[k] = fsub2_(fmul2_(c, r), fmul2_(s, i));
        si[k] = ffma2_(c, i, fmul2_(s, r));
    }
}

// ---------------------------------------------------------------------------
// CNOT: control bit BC, target bit BT.
// ---------------------------------------------------------------------------
template<int BC, int BT>
__device__ __forceinline__ void cnot_gate(float2 sr[16], float2 si[16], int lane) {
    if constexpr (BC >= 5 && BT >= 5) {
        constexpr unsigned msk = 1u << (BT - 5);
        const bool ctl = (lane >> (BC - 5)) & 1;
        #pragma unroll
        for (int k = 0; k < 16; ++k) {
            float2 qr, qi;
            qr.x = __shfl_xor_sync(0xffffffffu, sr[k].x, msk);
            qr.y = __shfl_xor_sync(0xffffffffu, sr[k].y, msk);
            qi.x = __shfl_xor_sync(0xffffffffu, si[k].x, msk);
            qi.y = __shfl_xor_sync(0xffffffffu, si[k].y, msk);
            sr[k].x = ctl ? qr.x : sr[k].x;  sr[k].y = ctl ? qr.y : sr[k].y;
            si[k].x = ctl ? qi.x : si[k].x;  si[k].y = ctl ? qi.y : si[k].y;
        }
    } else if constexpr (BC >= 5 && BT >= 1) {
        constexpr int pb = BT - 1;
        const bool ctl = (lane >> (BC - 5)) & 1;
        #pragma unroll
        for (int k = 0; k < 16; ++k) {
            if (!((k >> pb) & 1)) {
                const int k2 = k | (1 << pb);
                float2 r0 = sr[k], r1 = sr[k2];
                float2 i0 = si[k], i1 = si[k2];
                sr[k].x  = ctl ? r1.x : r0.x;  sr[k].y  = ctl ? r1.y : r0.y;
                sr[k2].x = ctl ? r0.x : r1.x;  sr[k2].y = ctl ? r0.y : r1.y;
                si[k].x  = ctl ? i1.x : i0.x;  si[k].y  = ctl ? i1.y : i0.y;
                si[k2].x = ctl ? i0.x : i1.x;  si[k2].y = ctl ? i0.y : i1.y;
            }
        }
    } else if constexpr (BC >= 5 && BT == 0) {
        const bool ctl = (lane >> (BC - 5)) & 1;
        #pragma unroll
        for (int k = 0; k < 16; ++k) {
            float2 vr = sr[k], vi = si[k];
            sr[k].x = ctl ? vr.y : vr.x;  sr[k].y = ctl ? vr.x : vr.y;
            si[k].x = ctl ? vi.y : vi.x;  si[k].y = ctl ? vi.x : vi.y;
        }
    } else if constexpr (BC >= 1 && BT >= 5) {
        constexpr unsigned msk = 1u << (BT - 5);
        constexpr int pb = BC - 1;
        #pragma unroll
        for (int k = 0; k < 16; ++k) {
            if ((k >> pb) & 1) {
                sr[k].x = __shfl_xor_sync(0xffffffffu, sr[k].x, msk);
                sr[k].y = __shfl_xor_sync(0xffffffffu, sr[k].y, msk);
                si[k].x = __shfl_xor_sync(0xffffffffu, si[k].x, msk);
                si[k].y = __shfl_xor_sync(0xffffffffu, si[k].y, msk);
            }
        }
    } else if constexpr (BC >= 1 && BT >= 1) {
        constexpr int pbc = BC - 1, pbt = BT - 1;
        #pragma unroll
        for (int k = 0; k < 16; ++k) {
            if (((k >> pbc) & 1) && !((k >> pbt) & 1)) {
                const int k2 = k | (1 << pbt);
                float2 t;
                t = sr[k]; sr[k] = sr[k2]; sr[k2] = t;
                t = si[k]; si[k] = si[k2]; si[k2] = t;
            }
        }
    } else if constexpr (BC >= 1 && BT == 0) {
        constexpr int pb = BC - 1;
        #pragma unroll
        for (int k = 0; k < 16; ++k) {
            if ((k >> pb) & 1) {
                float t;
                t = sr[k].x; sr[k].x = sr[k].y; sr[k].y = t;
                t = si[k].x; si[k].x = si[k].y; si[k].y = t;
            }
        }
    } else if constexpr (BC == 0 && BT >= 5) {
        constexpr unsigned msk = 1u << (BT - 5);
        #pragma unroll
        for (int k = 0; k < 16; ++k) {
            sr[k].y = __shfl_xor_sync(0xffffffffu, sr[k].y, msk);
            si[k].y = __shfl_xor_sync(0xffffffffu, si[k].y, msk);
        }
    } else {
        constexpr int pb = BT - 1;
        #pragma unroll
        for (int k = 0; k < 16; ++k) {
            if (!((k >> pb) & 1)) {
                const int k2 = k | (1 << pb);
                float t;
                t = sr[k].y; sr[k].y = sr[k2].y; sr[k2].y = t;
                t = si[k].y; si[k].y = si[k2].y; si[k2].y = t;
            }
        }
    }
}

template<int R, int W>
__device__ __forceinline__ void cnot_chain(float2 sr[16], float2 si[16], int lane) {
    if constexpr (W < NQ) {
        constexpr int T = (W + R) % NQ;
        cnot_gate<9 - W, 9 - T>(sr, si, lane);
        cnot_chain<R, W + 1>(sr, si, lane);
    }
}

// ---------------------------------------------------------------------------
// Main kernel: one warp per sample; state in registers (f32x2 packed).
// Circuit form: T0*init, Y0, [E_l, P_{l-1}, Y_l] for l=1..5, P_5, probs.
// (Final diagonal Domega_5 dropped: measurement-invariant.)
// ---------------------------------------------------------------------------
__global__ void __launch_bounds__(256, 2) qcnn_kernel(
    const float* __restrict__ x,
    const float* __restrict__ fc_w,
    const float* __restrict__ fc_b,
    float* __restrict__ out)
{
    const int warp = (blockIdx.x * blockDim.x + threadIdx.x) >> 5;
    const int lane = threadIdx.x & 31;
    if (warp >= BATCH) return;

    // --- initial product state magnitudes -----------------------------------
    const float* xb = x + warp * NQ;
    float cq[NQ], sq[NQ];
    #pragma unroll
    for (int q = 0; q < NQ; ++q) {
        float h = 0.5f * __ldg(xb + q);
        sincosf(h, &sq[q], &cq[q]);
    }
    float A = 1.f;
    #pragma unroll
    for (int q = 0; q < 5; ++q)
        A *= ((lane >> (4 - q)) & 1) ? sq[q] : cq[q];

    float m[16];
    m[0] = A;
    #pragma unroll
    for (int t = 0; t < 4; ++t) {
        const int q = 8 - t;
        const int sz = 1 << t;
        #pragma unroll
        for (int k = sz - 1; k >= 0; --k) {
            float v = m[k];
            m[k + sz] = v * sq[q];
            m[k]      = v * cq[q];
        }
    }
    // amp = mag * T0 (T0 already contains (-i)^popc and Dphi_0)
    float2 sr[16], si[16];
    #pragma unroll
    for (int k = 0; k < 16; ++k) {
        float4 t = __ldg(&g_T0[k * 32 + lane]);
        float2 mag2 = make_float2(m[k] * cq[9], m[k] * sq[9]);
        sr[k] = fmul2_(mag2, make_float2(t.x, t.z));
        si[k] = fmul2_(mag2, make_float2(t.y, t.w));
    }

    // --- circuit -------------------------------------------------------------
    ry_layer<0>(sr, si, lane, g_ry[0]);
    #pragma unroll 1
    for (int l = 1; l <= 5; ++l) {
        apply_diag(sr, si, lane, g_E[l - 1]);
        switch (l - 1) {   // P_{l-1}: r = l
            case 0: cnot_chain<1, 0>(sr, si, lane); break;
            case 1: cnot_chain<2, 0>(sr, si, lane); break;
            case 2: cnot_chain<3, 0>(sr, si, lane); break;
            case 3: cnot_chain<4, 0>(sr, si, lane); break;
            default: cnot_chain<5, 0>(sr, si, lane); break;
        }
        ry_layer<0>(sr, si, lane, g_ry[l]);
    }
    cnot_chain<6, 0>(sr, si, lane);   // P_5

    // --- epilogue: sum_i w_i * |psi_i|^2 ------------------------------------
    float f[NQ];
    #pragma unroll
    for (int q = 0; q < NQ; ++q) f[q] = __ldg(fc_w + q);

    float wl = 0.f;
    #pragma unroll
    for (int q = 0; q < 5; ++q)
        wl += ((lane >> (4 - q)) & 1) ? -f[q] : f[q];

    float2 acc2 = make_float2(0.f, 0.f);
    #pragma unroll
    for (int k = 0; k < 16; ++k) {
        float base = wl;
        base += (k & 1) ? -f[8] : f[8];
        base += (k & 2) ? -f[7] : f[7];
        base += (k & 4) ? -f[6] : f[6];
        base += (k & 8) ? -f[5] : f[5];
        float2 w2 = make_float2(base + f[9], base - f[9]);
        float2 p2 = ffma2_(si[k], si[k], fmul2_(sr[k], sr[k]));
        acc2 = ffma2_(w2, p2, acc2);
    }
    float acc = acc2.x + acc2.y;
    #pragma unroll
    for (int off = 16; off; off >>= 1)
        acc += __shfl_xor_sync(0xffffffffu, acc, off);

    if (lane == 0) out[warp] = acc + __ldg(fc_b);
}

// ---------------------------------------------------------------------------
extern "C" void kernel_launch(void* const* d_in, const int* in_sizes, int n_in,
                              void* d_out, int out_size) {
    const float* x    = (const float*)d_in[0];   // (16384, 10)
    const float* ql   = (const float*)d_in[1];   // (6, 10, 3)
    const float* fcw  = (const float*)d_in[2];   // (1, 10)
    const float* fcb  = (const float*)d_in[3];   // (1,)
    float* out = (float*)d_out;                  // (16384, 1)

    table_kernel<<<2, 256>>>(ql);
    qcnn_kernel<<<BATCH / 8, 256>>>(x, fcw, fcb, out);
}

// round 6
// speedup vs baseline: 1.5843x; 1.0237x over previous
#include <cuda_runtime.h>

#define NQ      10
#define DIM     1024
#define NLAYERS 6
#define BATCH   16384

// Precomputed tables (sample-independent):
//  g_ry[l][q] = (cos θ/2, sin θ/2)
//  g_T0[idx]  = init phase pairs: (-i)^popc(n) * Dphi_0[n]
//  g_E[l-1][idx] = fused diagonal between RY layer l-1 and l
// idx = k*32 + lane; pair covers amplitudes n0 = lane*32+k*2, n1 = n0+1
__device__ float2 g_ry[NLAYERS][NQ];
__device__ __align__(16) float4 g_T0[512];
__device__ __align__(16) float4 g_E[5][512];

// ---------------------------------------------------------------------------
// Compile-time GF(2) algebra for the final CNOT layer (r=6), virtualized into
// the epilogue: S6 = tau_0 ∘ ... ∘ tau_9 (tau_9 applied first to the index).
// s6inv_map applies S6^{-1} (= tau_9 ∘ ... ∘ tau_0, tau_0 first).
// ---------------------------------------------------------------------------
__host__ __device__ constexpr int s6inv_map(int m) {
    for (int w = 0; w < 10; ++w) {
        int cb = 9 - w, tb = 9 - ((w + 6) % 10);
        m ^= ((m >> cb) & 1) << tb;
    }
    return m;
}
__host__ __device__ constexpr int s6inv_row_bit(int b) {   // mask r: <r,m> = bit b of S6^{-1} m
    int r = 0;
    for (int j = 0; j < 10; ++j)
        r |= ((s6inv_map(1 << j) >> b) & 1) << j;
    return r;
}

// ---------------------------------------------------------------------------
// Packed f32x2 helpers (SASS FFMA2/FMUL2 — ptxas never emits these from C++)
// ---------------------------------------------------------------------------
__device__ __forceinline__ float2 ffma2_(float2 a, float2 b, float2 c) {
    float2 d;
    asm("{\n\t.reg .b64 A,B,C,D;\n\t"
        "mov.b64 A,{%2,%3};\n\t mov.b64 B,{%4,%5};\n\t mov.b64 C,{%6,%7};\n\t"
        "fma.rn.f32x2 D,A,B,C;\n\t"
        "mov.b64 {%0,%1},D;\n\t}"
        : "=f"(d.x), "=f"(d.y)
        : "f"(a.x), "f"(a.y), "f"(b.x), "f"(b.y), "f"(c.x), "f"(c.y));
    return d;
}
__device__ __forceinline__ float2 fmul2_(float2 a, float2 b) {
    float2 d;
    asm("{\n\t.reg .b64 A,B,D;\n\t"
        "mov.b64 A,{%2,%3};\n\t mov.b64 B,{%4,%5};\n\t"
        "mul.rn.f32x2 D,A,B;\n\t"
        "mov.b64 {%0,%1},D;\n\t}"
        : "=f"(d.x), "=f"(d.y)
        : "f"(a.x), "f"(a.y), "f"(b.x), "f"(b.y));
    return d;
}
__device__ __forceinline__ float2 fsub2_(float2 a, float2 b) {
    float2 d;
    asm("{\n\t.reg .b64 A,B,D;\n\t"
        "mov.b64 A,{%2,%3};\n\t mov.b64 B,{%4,%5};\n\t"
        "sub.rn.f32x2 D,A,B;\n\t"
        "mov.b64 {%0,%1},D;\n\t}"
        : "=f"(d.x), "=f"(d.y)
        : "f"(a.x), "f"(a.y), "f"(b.x), "f"(b.y));
    return d;
}
__device__ __forceinline__ float2 bc2(float v) { return make_float2(v, v); }

// ---------------------------------------------------------------------------
// Pre-kernel: RY coefficients + diagonal phase tables (unchanged from R4).
// ---------------------------------------------------------------------------
__device__ __forceinline__ float sum_signed(int n, const float* ql, int l, int off) {
    float a = 0.f;
    #pragma unroll
    for (int q = 0; q < NQ; ++q) {
        float v = ql[(l * NQ + q) * 3 + off];
        a += ((n >> (9 - q)) & 1) ? v : -v;
    }
    return 0.5f * a;
}

__global__ void table_kernel(const float* __restrict__ ql) {
    int idx = blockIdx.x * blockDim.x + threadIdx.x;
    if (idx < NLAYERS * NQ) {
        int l = idx / NQ, q = idx % NQ;
        float s, c; sincosf(0.5f * ql[(l * NQ + q) * 3 + 1], &s, &c);
        g_ry[l][q] = make_float2(c, s);
    }
    if (idx >= 512) return;
    int k = idx >> 5, lane = idx & 31;
    int n0 = lane * 32 + k * 2;

    {   // T0: (-i)^popc(n) * Dphi_0[n]
        float cs[2], sn[2];
        #pragma unroll
        for (int comp = 0; comp < 2; ++comp) {
            int n = n0 + comp;
            float ang = -1.57079632679f * __popc(n) + sum_signed(n, ql, 0, 0);
            sincosf(ang, &sn[comp], &cs[comp]);
        }
        g_T0[idx] = make_float4(cs[0], sn[0], cs[1], sn[1]);
    }
    // E_l for l = 1..5: E[m] = Domega_{l-1}[m] * Dphi_l[sigma_{l-1}^{-1}(m)]
    #pragma unroll 1
    for (int l = 1; l <= 5; ++l) {
        float cs[2], sn[2];
        #pragma unroll
        for (int comp = 0; comp < 2; ++comp) {
            int n = n0 + comp;
            float angw = sum_signed(n, ql, l - 1, 2);
            int p = n;             // sigma^{-1}: apply tau_0 .. tau_9 in order
            #pragma unroll
            for (int w = 0; w < NQ; ++w) {
                int cbit = 9 - w;
                int tbit = 9 - ((w + l) % NQ);
                p ^= ((p >> cbit) & 1) << tbit;
            }
            float angp = sum_signed(p, ql, l, 0);
            sincosf(angw + angp, &sn[comp], &cs[comp]);
        }
        g_E[l - 1][idx] = make_float4(cs[0], sn[0], cs[1], sn[1]);
    }
}

// ---------------------------------------------------------------------------
// State layout: amplitude n: bits 9..5 lane, 4..1 pack k, 0 comp.
// Qubit q acts on bit 9-q.
// ---------------------------------------------------------------------------

// Plain RY gate on lane bit L.
template<int L>
__device__ __forceinline__ void ry_lane_gate(float2 sr[16], float2 si[16], int lane,
                                             float2 g) {
    constexpr unsigned msk = 1u << L;
    const bool hi = (lane >> L) & 1;
    const float2 c2 = bc2(g.x);
    const float2 s2 = bc2(hi ? g.y : -g.y);
    #pragma unroll
    for (int k = 0; k < 16; ++k) {
        float2 qr, qi;
        qr.x = __shfl_xor_sync(0xffffffffu, sr[k].x, msk);
        qr.y = __shfl_xor_sync(0xffffffffu, sr[k].y, msk);
        qi.x = __shfl_xor_sync(0xffffffffu, si[k].x, msk);
        qi.y = __shfl_xor_sync(0xffffffffu, si[k].y, msk);
        sr[k] = ffma2_(s2, qr, fmul2_(c2, sr[k]));
        si[k] = ffma2_(s2, qi, fmul2_(c2, si[k]));
    }
}

// Plain RY gate on local bit B (1..4 = pack bit B-1; 0 = comp bit).
template<int B>
__device__ __forceinline__ void ry_local_gate(float2 sr[16], float2 si[16], float2 g) {
    if constexpr (B >= 1) {
        constexpr int pb = B - 1;
        const float2 cl2 = bc2(g.x), sl2 = bc2(g.y), nsl2 = bc2(-g.y);
        #pragma unroll
        for (int t = 0; t < 8; ++t) {
            const int k  = ((t >> pb) << (pb + 1)) | (t & ((1 << pb) - 1));
            const int k2 = k | (1 << pb);
            float2 Ar = sr[k], Ai = si[k], Br = sr[k2], Bi = si[k2];
            sr[k]  = ffma2_(nsl2, Br, fmul2_(cl2, Ar));
            si[k]  = ffma2_(nsl2, Bi, fmul2_(cl2, Ai));
            sr[k2] = ffma2_(cl2, Br, fmul2_(sl2, Ar));
            si[k2] = ffma2_(cl2, Bi, fmul2_(sl2, Ai));
        }
    } else {
        const float2 c2 = bc2(g.x);
        const float2 sp2 = make_float2(-g.y, g.y);
        #pragma unroll
        for (int k = 0; k < 16; ++k) {
            float2 vr = sr[k], vi = si[k];
            float2 wr = make_float2(vr.y, vr.x);
            float2 wi = make_float2(vi.y, vi.x);
            sr[k] = ffma2_(sp2, wr, fmul2_(c2, vr));
            si[k] = ffma2_(sp2, wi, fmul2_(c2, vi));
        }
    }
}

// Fused stage: CNOT(local control bit Bc -> lane target bit L) followed by
// RY on the target qubit. Same pair mask as the plain lane gate — the CNOT's
// conditional swap becomes a compile-time (alpha,beta) coefficient swap.
//   out = alpha*v + beta*p;  ctl=0: (c, sigma)   ctl=1: (sigma, c)
// where sigma = (my t-bit ? s : -s).
template<int Bc, int L>
__device__ __forceinline__ void fused_cnot_ry(float2 sr[16], float2 si[16], int lane,
                                              float2 g) {
    constexpr unsigned msk = 1u << L;
    const bool hi = (lane >> L) & 1;
    const float sg = hi ? g.y : -g.y;
    if constexpr (Bc == 0) {
        // comp-bit control: components differ
        const float2 A = make_float2(g.x, sg);
        const float2 B = make_float2(sg, g.x);
        #pragma unroll
        for (int k = 0; k < 16; ++k) {
            float2 qr, qi;
            qr.x = __shfl_xor_sync(0xffffffffu, sr[k].x, msk);
            qr.y = __shfl_xor_sync(0xffffffffu, sr[k].y, msk);
            qi.x = __shfl_xor_sync(0xffffffffu, si[k].x, msk);
            qi.y = __shfl_xor_sync(0xffffffffu, si[k].y, msk);
            sr[k] = ffma2_(B, qr, fmul2_(A, sr[k]));
            si[k] = ffma2_(B, qi, fmul2_(A, si[k]));
        }
    } else {
        const float2 c2 = bc2(g.x), s2 = bc2(sg);
        #pragma unroll
        for (int k = 0; k < 16; ++k) {
            float2 qr, qi;
            qr.x = __shfl_xor_sync(0xffffffffu, sr[k].x, msk);
            qr.y = __shfl_xor_sync(0xffffffffu, sr[k].y, msk);
            qi.x = __shfl_xor_sync(0xffffffffu, si[k].x, msk);
            qi.y = __shfl_xor_sync(0xffffffffu, si[k].y, msk);
            const bool ctl = (k >> (Bc - 1)) & 1;       // compile-time after unroll
            const float2 A = ctl ? s2 : c2;
            const float2 B = ctl ? c2 : s2;
            sr[k] = ffma2_(B, qr, fmul2_(A, sr[k]));
            si[k] = ffma2_(B, qi, fmul2_(A, si[k]));
        }
    }
}

// ---------------------------------------------------------------------------
// Standalone CNOT (unchanged cases from R4): control bit BC, target bit BT.
// ---------------------------------------------------------------------------
template<int BC, int BT>
__device__ __forceinline__ void cnot_gate(float2 sr[16], float2 si[16], int lane) {
    if constexpr (BC >= 5 && BT >= 5) {
        constexpr unsigned msk = 1u << (BT - 5);
        const bool ctl = (lane >> (BC - 5)) & 1;
        #pragma unroll
        for (int k = 0; k < 16; ++k) {
            float2 qr, qi;
            qr.x = __shfl_xor_sync(0xffffffffu, sr[k].x, msk);
            qr.y = __shfl_xor_sync(0xffffffffu, sr[k].y, msk);
            qi.x = __shfl_xor_sync(0xffffffffu, si[k].x, msk);
            qi.y = __shfl_xor_sync(0xffffffffu, si[k].y, msk);
            sr[k].x = ctl ? qr.x : sr[k].x;  sr[k].y = ctl ? qr.y : sr[k].y;
            si[k].x = ctl ? qi.x : si[k].x;  si[k].y = ctl ? qi.y : si[k].y;
        }
    } else if constexpr (BC >= 5 && BT >= 1) {
        constexpr int pb = BT - 1;
        const bool ctl = (lane >> (BC - 5)) & 1;
        #pragma unroll
        for (int k = 0; k < 16; ++k) {
            if (!((k >> pb) & 1)) {
                const int k2 = k | (1 << pb);
                float2 r0 = sr[k], r1 = sr[k2];
                float2 i0 = si[k], i1 = si[k2];
                sr[k].x  = ctl ? r1.x : r0.x;  sr[k].y  = ctl ? r1.y : r0.y;
                sr[k2].x = ctl ? r0.x : r1.x;  sr[k2].y = ctl ? r0.y : r1.y;
                si[k].x  = ctl ? i1.x : i0.x;  si[k].y  = ctl ? i1.y : i0.y;
                si[k2].x = ctl ? i0.x : i1.x;  si[k2].y = ctl ? i0.y : i1.y;
            }
        }
    } else if constexpr (BC >= 5 && BT == 0) {
        const bool ctl = (lane >> (BC - 5)) & 1;
        #pragma unroll
        for (int k = 0; k < 16; ++k) {
            float2 vr = sr[k], vi = si[k];
            sr[k].x = ctl ? vr.y : vr.x;  sr[k].y = ctl ? vr.x : vr.y;
            si[k].x = ctl ? vi.y : vi.x;  si[k].y = ctl ? vi.x : vi.y;
        }
    } else if constexpr (BC >= 1 && BT >= 5) {
        constexpr unsigned msk = 1u << (BT - 5);
        constexpr int pb = BC - 1;
        #pragma unroll
        for (int k = 0; k < 16; ++k) {
            if ((k >> pb) & 1) {
                sr[k].x = __shfl_xor_sync(0xffffffffu, sr[k].x, msk);
                sr[k].y = __shfl_xor_sync(0xffffffffu, sr[k].y, msk);
                si[k].x = __shfl_xor_sync(0xffffffffu, si[k].x, msk);
                si[k].y = __shfl_xor_sync(0xffffffffu, si[k].y, msk);
            }
        }
    } else if constexpr (BC >= 1 && BT >= 1) {
        constexpr int pbc = BC - 1, pbt = BT - 1;
        #pragma unroll
        for (int k = 0; k < 16; ++k) {
            if (((k >> pbc) & 1) && !((k >> pbt) & 1)) {
                const int k2 = k | (1 << pbt);
                float2 t;
                t = sr[k]; sr[k] = sr[k2]; sr[k2] = t;
                t = si[k]; si[k] = si[k2]; si[k2] = t;
            }
        }
    } else if constexpr (BC >= 1 && BT == 0) {
        constexpr int pb = BC - 1;
        #pragma unroll
        for (int k = 0; k < 16; ++k) {
            if ((k >> pb) & 1) {
                float t;
                t = sr[k].x; sr[k].x = sr[k].y; sr[k].y = t;
                t = si[k].x; si[k].x = si[k].y; si[k].y = t;
            }
        }
    } else if constexpr (BC == 0 && BT >= 5) {
        constexpr unsigned msk = 1u << (BT - 5);
        #pragma unroll
        for (int k = 0; k < 16; ++k) {
            sr[k].y = __shfl_xor_sync(0xffffffffu, sr[k].y, msk);
            si[k].y = __shfl_xor_sync(0xffffffffu, si[k].y, msk);
        }
    } else {
        constexpr int pb = BT - 1;
        #pragma unroll
        for (int k = 0; k < 16; ++k) {
            if (!((k >> pb) & 1)) {
                const int k2 = k | (1 << pb);
                float t;
                t = sr[k].y; sr[k].y = sr[k2].y; sr[k2].y = t;
                t = si[k].y; si[k].y = si[k2].y; si[k2].y = t;
            }
        }
    }
}

// fused diagonal: per pack complex multiply by table phase
__device__ __forceinline__ void apply_diag(float2 sr[16], float2 si[16], int lane,
                                           const float4* __restrict__ tbl) {
    #pragma unroll
    for (int k = 0; k < 16; ++k) {
        float4 t = __ldg(tbl + k * 32 + lane);
        float2 c = make_float2(t.x, t.z);
        float2 s = make_float2(t.y, t.w);
        float2 r = sr[k], i = si[k];
        sr[k] = fsub2_(fmul2_(c, r), fmul2_(s, i));
        si[k] = ffma2_(c, i, fmul2_(s, r));
    }
}

// ---------------------------------------------------------------------------
// Layer scheduling (layer l, CNOT shift r = l):
//  1. diag E_l
//  2. standalone taus w = 0..9-r  (no wrap; index order)
//  3. fused stages   w = 10-r..9: CNOT(ctl bit 9-w local, tgt bit 19-w-r lane)
//     + RY gate on qubit w+r-10
//  4. remaining RY gates q = r..9
// ---------------------------------------------------------------------------
template<int R, int W>
__device__ __forceinline__ void standalone_taus(float2 sr[16], float2 si[16], int lane) {
    if constexpr (W <= 9 - R) {
        cnot_gate<9 - W, 9 - W - R>(sr, si, lane);
        standalone_taus<R, W + 1>(sr, si, lane);
    }
}
template<int R, int W>
__device__ __forceinline__ void fused_stages(float2 sr[16], float2 si[16], int lane,
                                             const float2* __restrict__ ry) {
    if constexpr (W <= 9) {
        constexpr int Bc = 9 - W;          // local control bit (0..R-1)
        constexpr int Bt = 19 - W - R;     // lane target bit (5..9)
        fused_cnot_ry<Bc, Bt - 5>(sr, si, lane, __ldg(ry + (W + R - 10)));
        fused_stages<R, W + 1>(sr, si, lane, ry);
    }
}
template<int R, int Q>
__device__ __forceinline__ void remaining_gates(float2 sr[16], float2 si[16], int lane,
                                                const float2* __restrict__ ry) {
    if constexpr (Q <= 9) {
        if constexpr (Q <= 4)
            ry_lane_gate<4 - Q>(sr, si, lane, __ldg(ry + Q));
        else
            ry_local_gate<9 - Q>(sr, si, __ldg(ry + Q));
        remaining_gates<R, Q + 1>(sr, si, lane, ry);
    }
}
template<int L>
__device__ __forceinline__ void fused_layer(float2 sr[16], float2 si[16], int lane) {
    apply_diag(sr, si, lane, g_E[L - 1]);
    standalone_taus<L, 0>(sr, si, lane);
    fused_stages<L, 10 - L>(sr, si, lane, g_ry[L]);
    remaining_gates<L, L>(sr, si, lane, g_ry[L]);
}

// ---------------------------------------------------------------------------
// Main kernel.
// ---------------------------------------------------------------------------
__global__ void __launch_bounds__(256, 2) qcnn_kernel(
    const float* __restrict__ x,
    const float* __restrict__ fc_w,
    const float* __restrict__ fc_b,
    float* __restrict__ out)
{
    const int warp = (blockIdx.x * blockDim.x + threadIdx.x) >> 5;
    const int lane = threadIdx.x & 31;
    if (warp >= BATCH) return;

    // --- initial product state magnitudes -----------------------------------
    const float* xb = x + warp * NQ;
    float cq[NQ], sq[NQ];
    #pragma unroll
    for (int q = 0; q < NQ; ++q) {
        float h = 0.5f * __ldg(xb + q);
        sincosf(h, &sq[q], &cq[q]);
    }
    float A = 1.f;
    #pragma unroll
    for (int q = 0; q < 5; ++q)
        A *= ((lane >> (4 - q)) & 1) ? sq[q] : cq[q];

    float m[16];
    m[0] = A;
    #pragma unroll
    for (int t = 0; t < 4; ++t) {
        const int q = 8 - t;
        const int sz = 1 << t;
        #pragma unroll
        for (int k = sz - 1; k >= 0; --k) {
            float v = m[k];
            m[k + sz] = v * sq[q];
            m[k]      = v * cq[q];
        }
    }
    float2 sr[16], si[16];
    #pragma unroll
    for (int k = 0; k < 16; ++k) {
        float4 t = __ldg(&g_T0[k * 32 + lane]);
        float2 mag2 = make_float2(m[k] * cq[9], m[k] * sq[9]);
        sr[k] = fmul2_(mag2, make_float2(t.x, t.z));
        si[k] = fmul2_(mag2, make_float2(t.y, t.w));
    }

    // --- circuit -------------------------------------------------------------
    remaining_gates<0, 0>(sr, si, lane, g_ry[0]);   // Y_0 (no preceding P)
    fused_layer<1>(sr, si, lane);
    fused_layer<2>(sr, si, lane);
    fused_layer<3>(sr, si, lane);
    fused_layer<4>(sr, si, lane);
    fused_layer<5>(sr, si, lane);
    // P_5 (r=6) fully virtualized into the epilogue weights below.

    // --- epilogue: out = sum_m w_{S6^{-1} m} |psi_m|^2 -----------------------
    float F[NQ];
    #pragma unroll
    for (int q = 0; q < NQ; ++q) {
        const int lm = (s6inv_row_bit(9 - q) >> 5) & 31;   // constant-folded
        float fq = __ldg(fc_w + q);
        F[q] = (__popc(lane & lm) & 1) ? -fq : fq;
    }
    float2 acc2 = make_float2(0.f, 0.f);
    #pragma unroll
    for (int k = 0; k < 16; ++k) {
        float w0 = 0.f, w1 = 0.f;
        #pragma unroll
        for (int q = 0; q < NQ; ++q) {
            const int pm = s6inv_row_bit(9 - q) & 31;      // constant-folded
            w0 = (__popc((k << 1) & pm) & 1)       ? (w0 - F[q]) : (w0 + F[q]);
            w1 = (__popc(((k << 1) | 1) & pm) & 1) ? (w1 - F[q]) : (w1 + F[q]);
        }
        float2 p2 = ffma2_(si[k], si[k], fmul2_(sr[k], sr[k]));
        acc2 = ffma2_(make_float2(w0, w1), p2, acc2);
    }
    float acc = acc2.x + acc2.y;
    #pragma unroll
    for (int off = 16; off; off >>= 1)
        acc += __shfl_xor_sync(0xffffffffu, acc, off);

    if (lane == 0) out[warp] = acc + __ldg(fc_b);
}

// ---------------------------------------------------------------------------
extern "C" void kernel_launch(void* const* d_in, const int* in_sizes, int n_in,
                              void* d_out, int out_size) {
    const float* x    = (const float*)d_in[0];   // (16384, 10)
    const float* ql   = (const float*)d_in[1];   // (6, 10, 3)
    const float* fcw  = (const float*)d_in[2];   // (1, 10)
    const float* fcb  = (const float*)d_in[3];   // (1,)
    float* out = (float*)d_out;                  // (16384, 1)

    table_kernel<<<2, 256>>>(ql);
    qcnn_kernel<<<BATCH / 8, 256>>>(x, fcw, fcb, out);
}